// round 13
// baseline (speedup 1.0000x reference)
#include <cuda_runtime.h>
#include <math.h>

// Problem constants
#define N_IMG 4
#define C_DIM 256
#define H_DIM 50
#define W_DIM 50
#define HW (H_DIM * W_DIM)
#define PH 7
#define PW 7
#define NBINS (PH * PW)
#define N_ROI 1024
#define OUT_PER_ROI (C_DIM * NBINS)   // 12544 floats
#define SPATIAL_SCALE 0.0625f
#define ROW_STRIDE (W_DIM * C_DIM)    // floats per h-row in NHWC

// fl(1/7) in fp32 — XLA rewrites (x / 7) into (x * fl(1/7)); we must match it.
#define RCP_7 0.14285714924335479736328125f

// Scratch: x transposed to [N][H][W][C] (channels-last) = 10.24 MB
__device__ float g_xt[N_IMG * HW * C_DIM];

// Precomputed per-roi geometry (ints, computed once with exact XLA numerics)
__device__ int g_boff[N_ROI];        // image base offset in floats
__device__ int g_hs[N_ROI * PH];
__device__ int g_he[N_ROI * PH];
__device__ int g_ws[N_ROI * PW];
__device__ int g_we[N_ROI * PW];

// ---------------------------------------------------------------------------
// Vectorized transpose NCHW -> NHWC. 32(hw) x 32(c) tiles, float4 on both
// gmem sides. Block = (8, 32) = 256 threads, 4 elements/thread.
// Bank analysis: load-side STS (4tx+k)*33+ty -> banks 4tx+ty+k (distinct);
// store-side LDS.128 at 33ty+4tx -> conflict-free; gmem 128B-line aligned.
// Block (0,0,0) additionally precomputes all roi bin edges (256 thr x 4 rois)
// with exact XLA numerics.
// ---------------------------------------------------------------------------
__global__ void __launch_bounds__(256) transpose_kernel(const float* __restrict__ x,
                                                        const float* __restrict__ rois) {
    __shared__ float tile[32][33];   // [hw_local][c_local]

    if (blockIdx.x == 0 && blockIdx.y == 0 && blockIdx.z == 0) {
        const int tid = threadIdx.y * 8 + threadIdx.x;
        #pragma unroll
        for (int q = 0; q < 4; ++q) {
            const int roi = tid * 4 + q;   // 0..1023
            const float* r = rois + roi * 5;
            const int b  = (int)r[0];
            const int xs = (int)rintf(__fmul_rn(r[1], SPATIAL_SCALE));
            const int ys = (int)rintf(__fmul_rn(r[2], SPATIAL_SCALE));
            const int xe = (int)rintf(__fmul_rn(r[3], SPATIAL_SCALE));
            const int ye = (int)rintf(__fmul_rn(r[4], SPATIAL_SCALE));
            const float rw = (float)max(xe - xs + 1, 1);
            const float rh = (float)max(ye - ys + 1, 1);
            const float bh = __fmul_rn(rh, RCP_7);   // XLA reciprocal-multiply
            const float bw = __fmul_rn(rw, RCP_7);

            g_boff[roi] = b * (HW * C_DIM);
            #pragma unroll
            for (int p = 0; p < PH; ++p) {
                int hs = (int)floorf(__fmul_rn((float)p,        bh)) + ys;
                int he = (int)ceilf (__fmul_rn((float)p + 1.0f, bh)) + ys;
                int ws = (int)floorf(__fmul_rn((float)p,        bw)) + xs;
                int we = (int)ceilf (__fmul_rn((float)p + 1.0f, bw)) + xs;
                g_hs[roi * PH + p] = min(max(hs, 0), H_DIM);
                g_he[roi * PH + p] = min(max(he, 0), H_DIM);
                g_ws[roi * PW + p] = min(max(ws, 0), W_DIM);
                g_we[roi * PW + p] = min(max(we, 0), W_DIM);
            }
        }
    }

    const int n   = blockIdx.z;
    const int hw0 = blockIdx.x * 32;
    const int c0b = blockIdx.y * 32;

    // Load: float4 along hw. thread (tx in [0,8), ty in [0,32)).
    {
        const int c  = c0b + threadIdx.y;
        const int hw = hw0 + threadIdx.x * 4;
        if (hw + 3 < HW) {
            const float4 v = *(const float4*)&x[(n * C_DIM + c) * HW + hw];
            const int hl = threadIdx.x * 4;
            tile[hl + 0][threadIdx.y] = v.x;
            tile[hl + 1][threadIdx.y] = v.y;
            tile[hl + 2][threadIdx.y] = v.z;
            tile[hl + 3][threadIdx.y] = v.w;
        }
    }
    __syncthreads();

    // Store: float4 along c. thread: hw = hw0 + ty, c = c0b + tx*4.
    {
        const int hw = hw0 + threadIdx.y;
        if (hw < HW) {
            const int cl = threadIdx.x * 4;
            float4 v;
            v.x = tile[threadIdx.y][cl + 0];
            v.y = tile[threadIdx.y][cl + 1];
            v.z = tile[threadIdx.y][cl + 2];
            v.w = tile[threadIdx.y][cl + 3];
            *(float4*)&g_xt[(size_t)(n * HW + hw) * C_DIM + c0b + cl] = v;
        }
    }
}

// ---------------------------------------------------------------------------
// RoI max pooling — BYTE-IDENTICAL to the proven-best R9 kernel (49.0us).
// One block per (roi, ph-row). Grid = 1024 x 7.
// Block = 256 threads = 4 pw-groups x 64 lanes (float4 -> 256 channels).
// Each pw-group handles pw = grp, then pw = grp + 4.
// Hot loop: exact 2x2 (h,w) diamond, 4 independent LDG.128 in flight.
// ---------------------------------------------------------------------------
__global__ void __launch_bounds__(256, 6) roipool_kernel(float* __restrict__ out) {
    __shared__ float s_out[C_DIM * PW];   // [c][pw] = 7168 B

    const int roi = blockIdx.x;
    const int ph  = blockIdx.y;

    const int boff = __ldg(&g_boff[roi]);
    const int hs   = __ldg(&g_hs[roi * PH + ph]);
    const int he   = __ldg(&g_he[roi * PH + ph]);

    const int lane = threadIdx.x & 63;   // 64 lanes -> 256 channels via float4
    const int grp  = threadIdx.x >> 6;   // 4 pw-groups
    const int c0   = lane * 4;

    const float* __restrict__ base = g_xt + boff + c0;

    #pragma unroll 1
    for (int it = 0; it < 2; ++it) {
        const int pw = it * 4 + grp;
        if (pw < PW) {
            const int ws = __ldg(&g_ws[roi * PW + pw]);
            const int we = __ldg(&g_we[roi * PW + pw]);

            float m0 = -INFINITY, m1 = -INFINITY, m2 = -INFINITY, m3 = -INFINITY;
            const bool empty = (hs >= he) || (ws >= we);

            int h = hs;
            #pragma unroll 1
            for (; h + 1 < he; h += 2) {           // two rows per trip
                const float* p0 = base + h * ROW_STRIDE;
                const float* p1 = p0 + ROW_STRIDE;
                int w = ws;
                #pragma unroll 1
                for (; w + 1 < we; w += 2) {       // 2x2 diamond: 4 loads in flight
                    const float4 va = *(const float4*)(p0 + w * C_DIM);
                    const float4 vb = *(const float4*)(p0 + (w + 1) * C_DIM);
                    const float4 vc = *(const float4*)(p1 + w * C_DIM);
                    const float4 vd = *(const float4*)(p1 + (w + 1) * C_DIM);
                    m0 = fmaxf(fmaxf(fmaxf(m0, va.x), vb.x), fmaxf(vc.x, vd.x));
                    m1 = fmaxf(fmaxf(fmaxf(m1, va.y), vb.y), fmaxf(vc.y, vd.y));
                    m2 = fmaxf(fmaxf(fmaxf(m2, va.z), vb.z), fmaxf(vc.z, vd.z));
                    m3 = fmaxf(fmaxf(fmaxf(m3, va.w), vb.w), fmaxf(vc.w, vd.w));
                }
                if (w < we) {                      // odd-width remainder: 2 loads
                    const float4 va = *(const float4*)(p0 + w * C_DIM);
                    const float4 vc = *(const float4*)(p1 + w * C_DIM);
                    m0 = fmaxf(m0, fmaxf(va.x, vc.x));
                    m1 = fmaxf(m1, fmaxf(va.y, vc.y));
                    m2 = fmaxf(m2, fmaxf(va.z, vc.z));
                    m3 = fmaxf(m3, fmaxf(va.w, vc.w));
                }
            }
            if (h < he) {                          // odd-height remainder row
                const float* p0 = base + h * ROW_STRIDE;
                int w = ws;
                #pragma unroll 1
                for (; w + 1 < we; w += 2) {
                    const float4 va = *(const float4*)(p0 + w * C_DIM);
                    const float4 vb = *(const float4*)(p0 + (w + 1) * C_DIM);
                    m0 = fmaxf(m0, fmaxf(va.x, vb.x));
                    m1 = fmaxf(m1, fmaxf(va.y, vb.y));
                    m2 = fmaxf(m2, fmaxf(va.z, vb.z));
                    m3 = fmaxf(m3, fmaxf(va.w, vb.w));
                }
                if (w < we) {
                    const float4 va = *(const float4*)(p0 + w * C_DIM);
                    m0 = fmaxf(m0, va.x); m1 = fmaxf(m1, va.y);
                    m2 = fmaxf(m2, va.z); m3 = fmaxf(m3, va.w);
                }
            }
            if (empty) { m0 = m1 = m2 = m3 = 0.0f; }

            s_out[(c0 + 0) * PW + pw] = m0;
            s_out[(c0 + 1) * PW + pw] = m1;
            s_out[(c0 + 2) * PW + pw] = m2;
            s_out[(c0 + 3) * PW + pw] = m3;
        }
    }
    __syncthreads();

    // Store: out[roi, c, ph, pw] = s_out[c*7 + pw].
    float* __restrict__ obase = out + (size_t)roi * OUT_PER_ROI + ph * PW;
    #pragma unroll 1
    for (int i = threadIdx.x; i < C_DIM * PW; i += 256) {
        const int c  = i / PW;
        const int pw = i - c * PW;
        obase[c * NBINS + pw] = s_out[i];
    }
}

extern "C" void kernel_launch(void* const* d_in, const int* in_sizes, int n_in,
                              void* d_out, int out_size) {
    const float* x    = (const float*)d_in[0];
    const float* rois = (const float*)d_in[1];
    float* out        = (float*)d_out;

    (void)in_sizes; (void)n_in; (void)out_size;

    dim3 tgrid((HW + 31) / 32, C_DIM / 32, N_IMG);   // 79 x 8 x 4
    dim3 tblk(8, 32);
    transpose_kernel<<<tgrid, tblk>>>(x, rois);

    dim3 pgrid(N_ROI, PH);
    roipool_kernel<<<pgrid, 256>>>(out);
}

// round 14
// speedup vs baseline: 1.0255x; 1.0255x over previous
#include <cuda_runtime.h>
#include <math.h>

// Problem constants
#define N_IMG 4
#define C_DIM 256
#define H_DIM 50
#define W_DIM 50
#define HW (H_DIM * W_DIM)
#define PH 7
#define PW 7
#define NBINS (PH * PW)
#define N_ROI 1024
#define OUT_PER_ROI (C_DIM * NBINS)   // 12544 floats
#define SPATIAL_SCALE 0.0625f
#define ROW_STRIDE (W_DIM * C_DIM)    // floats per h-row in NHWC

// fl(1/7) in fp32 — XLA rewrites (x / 7) into (x * fl(1/7)); we must match it.
#define RCP_7 0.14285714924335479736328125f

// Scratch: x transposed to [N][H][W][C] (channels-last) = 10.24 MB
__device__ float g_xt[N_IMG * HW * C_DIM];

// Precomputed per-roi geometry (ints, computed once with exact XLA numerics)
__device__ int g_boff[N_ROI];        // image base offset in floats
__device__ int g_hs[N_ROI * PH];
__device__ int g_he[N_ROI * PH];
__device__ int g_ws[N_ROI * PW];
__device__ int g_we[N_ROI * PW];

// ---------------------------------------------------------------------------
// Classic tiled transpose NCHW -> NHWC. TILE=32, BLOCK_ROWS=8:
// 256 threads, 4 elements per thread, coalesced on both gmem sides,
// conflict-free smem ([33] padding). Per-image view: A[C][HW] -> B[HW][C].
// Block (0,0,0) additionally precomputes all roi bin edges (256 thr x 4 rois)
// with exact XLA numerics.
// ---------------------------------------------------------------------------
__global__ void __launch_bounds__(256) transpose_kernel(const float* __restrict__ x,
                                                        const float* __restrict__ rois) {
    __shared__ float tile[32][33];   // [c_local][hw_local]

    if (blockIdx.x == 0 && blockIdx.y == 0 && blockIdx.z == 0) {
        const int tid = threadIdx.y * 32 + threadIdx.x;   // block (32,8)
        #pragma unroll
        for (int q = 0; q < 4; ++q) {
            const int roi = tid * 4 + q;   // 0..1023
            const float* r = rois + roi * 5;
            const int b  = (int)r[0];
            const int xs = (int)rintf(__fmul_rn(r[1], SPATIAL_SCALE));
            const int ys = (int)rintf(__fmul_rn(r[2], SPATIAL_SCALE));
            const int xe = (int)rintf(__fmul_rn(r[3], SPATIAL_SCALE));
            const int ye = (int)rintf(__fmul_rn(r[4], SPATIAL_SCALE));
            const float rw = (float)max(xe - xs + 1, 1);
            const float rh = (float)max(ye - ys + 1, 1);
            const float bh = __fmul_rn(rh, RCP_7);   // XLA reciprocal-multiply
            const float bw = __fmul_rn(rw, RCP_7);

            g_boff[roi] = b * (HW * C_DIM);
            #pragma unroll
            for (int p = 0; p < PH; ++p) {
                int hs = (int)floorf(__fmul_rn((float)p,        bh)) + ys;
                int he = (int)ceilf (__fmul_rn((float)p + 1.0f, bh)) + ys;
                int ws = (int)floorf(__fmul_rn((float)p,        bw)) + xs;
                int we = (int)ceilf (__fmul_rn((float)p + 1.0f, bw)) + xs;
                g_hs[roi * PH + p] = min(max(hs, 0), H_DIM);
                g_he[roi * PH + p] = min(max(he, 0), H_DIM);
                g_ws[roi * PW + p] = min(max(ws, 0), W_DIM);
                g_we[roi * PW + p] = min(max(we, 0), W_DIM);
            }
        }
    }

    const int n   = blockIdx.z;
    const int hw0 = blockIdx.x * 32;
    const int c0b = blockIdx.y * 32;

    // Load: 4 rows of the 32x32 tile, coalesced along hw.
    {
        const int hw = hw0 + threadIdx.x;
        if (hw < HW) {
            #pragma unroll
            for (int j = 0; j < 32; j += 8) {
                const int c = c0b + threadIdx.y + j;
                tile[threadIdx.y + j][threadIdx.x] = x[(n * C_DIM + c) * HW + hw];
            }
        }
    }
    __syncthreads();

    // Store: 4 rows transposed, coalesced along c.
    {
        const int c = c0b + threadIdx.x;
        #pragma unroll
        for (int j = 0; j < 32; j += 8) {
            const int hw = hw0 + threadIdx.y + j;
            if (hw < HW) {
                g_xt[(size_t)(n * HW + hw) * C_DIM + c] = tile[threadIdx.x][threadIdx.y + j];
            }
        }
    }
}

// ---------------------------------------------------------------------------
// RoI max pooling — BYTE-IDENTICAL to the proven-best R9 kernel (48.5us).
// One block per (roi, ph-row). Grid = 1024 x 7.
// Block = 256 threads = 4 pw-groups x 64 lanes (float4 -> 256 channels).
// Each pw-group handles pw = grp, then pw = grp + 4.
// Hot loop: exact 2x2 (h,w) diamond, 4 independent LDG.128 in flight.
// ---------------------------------------------------------------------------
__global__ void __launch_bounds__(256, 6) roipool_kernel(float* __restrict__ out) {
    __shared__ float s_out[C_DIM * PW];   // [c][pw] = 7168 B

    const int roi = blockIdx.x;
    const int ph  = blockIdx.y;

    const int boff = __ldg(&g_boff[roi]);
    const int hs   = __ldg(&g_hs[roi * PH + ph]);
    const int he   = __ldg(&g_he[roi * PH + ph]);

    const int lane = threadIdx.x & 63;   // 64 lanes -> 256 channels via float4
    const int grp  = threadIdx.x >> 6;   // 4 pw-groups
    const int c0   = lane * 4;

    const float* __restrict__ base = g_xt + boff + c0;

    #pragma unroll 1
    for (int it = 0; it < 2; ++it) {
        const int pw = it * 4 + grp;
        if (pw < PW) {
            const int ws = __ldg(&g_ws[roi * PW + pw]);
            const int we = __ldg(&g_we[roi * PW + pw]);

            float m0 = -INFINITY, m1 = -INFINITY, m2 = -INFINITY, m3 = -INFINITY;
            const bool empty = (hs >= he) || (ws >= we);

            int h = hs;
            #pragma unroll 1
            for (; h + 1 < he; h += 2) {           // two rows per trip
                const float* p0 = base + h * ROW_STRIDE;
                const float* p1 = p0 + ROW_STRIDE;
                int w = ws;
                #pragma unroll 1
                for (; w + 1 < we; w += 2) {       // 2x2 diamond: 4 loads in flight
                    const float4 va = *(const float4*)(p0 + w * C_DIM);
                    const float4 vb = *(const float4*)(p0 + (w + 1) * C_DIM);
                    const float4 vc = *(const float4*)(p1 + w * C_DIM);
                    const float4 vd = *(const float4*)(p1 + (w + 1) * C_DIM);
                    m0 = fmaxf(fmaxf(fmaxf(m0, va.x), vb.x), fmaxf(vc.x, vd.x));
                    m1 = fmaxf(fmaxf(fmaxf(m1, va.y), vb.y), fmaxf(vc.y, vd.y));
                    m2 = fmaxf(fmaxf(fmaxf(m2, va.z), vb.z), fmaxf(vc.z, vd.z));
                    m3 = fmaxf(fmaxf(fmaxf(m3, va.w), vb.w), fmaxf(vc.w, vd.w));
                }
                if (w < we) {                      // odd-width remainder: 2 loads
                    const float4 va = *(const float4*)(p0 + w * C_DIM);
                    const float4 vc = *(const float4*)(p1 + w * C_DIM);
                    m0 = fmaxf(m0, fmaxf(va.x, vc.x));
                    m1 = fmaxf(m1, fmaxf(va.y, vc.y));
                    m2 = fmaxf(m2, fmaxf(va.z, vc.z));
                    m3 = fmaxf(m3, fmaxf(va.w, vc.w));
                }
            }
            if (h < he) {                          // odd-height remainder row
                const float* p0 = base + h * ROW_STRIDE;
                int w = ws;
                #pragma unroll 1
                for (; w + 1 < we; w += 2) {
                    const float4 va = *(const float4*)(p0 + w * C_DIM);
                    const float4 vb = *(const float4*)(p0 + (w + 1) * C_DIM);
                    m0 = fmaxf(m0, fmaxf(va.x, vb.x));
                    m1 = fmaxf(m1, fmaxf(va.y, vb.y));
                    m2 = fmaxf(m2, fmaxf(va.z, vb.z));
                    m3 = fmaxf(m3, fmaxf(va.w, vb.w));
                }
                if (w < we) {
                    const float4 va = *(const float4*)(p0 + w * C_DIM);
                    m0 = fmaxf(m0, va.x); m1 = fmaxf(m1, va.y);
                    m2 = fmaxf(m2, va.z); m3 = fmaxf(m3, va.w);
                }
            }
            if (empty) { m0 = m1 = m2 = m3 = 0.0f; }

            s_out[(c0 + 0) * PW + pw] = m0;
            s_out[(c0 + 1) * PW + pw] = m1;
            s_out[(c0 + 2) * PW + pw] = m2;
            s_out[(c0 + 3) * PW + pw] = m3;
        }
    }
    __syncthreads();

    // Store: out[roi, c, ph, pw] = s_out[c*7 + pw].
    float* __restrict__ obase = out + (size_t)roi * OUT_PER_ROI + ph * PW;
    #pragma unroll 1
    for (int i = threadIdx.x; i < C_DIM * PW; i += 256) {
        const int c  = i / PW;
        const int pw = i - c * PW;
        obase[c * NBINS + pw] = s_out[i];
    }
}

extern "C" void kernel_launch(void* const* d_in, const int* in_sizes, int n_in,
                              void* d_out, int out_size) {
    const float* x    = (const float*)d_in[0];
    const float* rois = (const float*)d_in[1];
    float* out        = (float*)d_out;

    (void)in_sizes; (void)n_in; (void)out_size;

    dim3 tgrid((HW + 31) / 32, C_DIM / 32, N_IMG);   // 79 x 8 x 4
    dim3 tblk(32, 8);
    transpose_kernel<<<tgrid, tblk>>>(x, rois);

    dim3 pgrid(N_ROI, PH);
    roipool_kernel<<<pgrid, 256>>>(out);
}

// round 15
// speedup vs baseline: 1.1755x; 1.1462x over previous
#include <cuda_runtime.h>
#include <math.h>

// Problem constants
#define N_IMG 4
#define C_DIM 256
#define H_DIM 50
#define W_DIM 50
#define HW (H_DIM * W_DIM)
#define PH 7
#define PW 7
#define NBINS (PH * PW)
#define N_ROI 1024
#define OUT_PER_ROI (C_DIM * NBINS)   // 12544 floats
#define SPATIAL_SCALE 0.0625f
#define ROW_STRIDE (W_DIM * C_DIM)    // floats per h-row (within a level)
#define LVL_STRIDE (N_IMG * HW * C_DIM)   // floats per sparse-table level

// fl(1/7) in fp32 — XLA rewrites (x / 7) into (x * fl(1/7)); we must match it.
#define RCP_7 0.14285714924335479736328125f

// Sparse range-max table, 4 levels. Level 0 = transposed input (NHWC).
// T_k[n][h][w][c] = max over w' in [w, w+2^k) of x_nhwc. 40.96 MB.
__device__ float g_tab[4 * LVL_STRIDE];

// Precomputed per-roi geometry (exact XLA numerics, computed once)
__device__ int  g_boff[N_ROI];        // image offset within a level (floats)
__device__ int  g_hs[N_ROI * PH];
__device__ int  g_he[N_ROI * PH];
__device__ int2 g_off[N_ROI * PW];    // (offA, offB) = level+column float offsets
                                      // offA < 0 marks an empty w-window

__device__ __forceinline__ float4 fmax4(float4 a, float4 b) {
    return make_float4(fmaxf(a.x, b.x), fmaxf(a.y, b.y),
                       fmaxf(a.z, b.z), fmaxf(a.w, b.w));
}

// ---------------------------------------------------------------------------
// Transpose NCHW -> NHWC into level 0 of g_tab (proven scalar version).
// Block (0,0,0) precomputes all roi bin edges + sparse-table lookup offsets.
// ---------------------------------------------------------------------------
__global__ void __launch_bounds__(1024) transpose_kernel(const float* __restrict__ x,
                                                         const float* __restrict__ rois) {
    __shared__ float tile[32][33];

    if (blockIdx.x == 0 && blockIdx.y == 0 && blockIdx.z == 0) {
        const int roi = threadIdx.y * 32 + threadIdx.x;   // 0..1023
        const float* r = rois + roi * 5;
        const int b  = (int)r[0];
        const int xs = (int)rintf(__fmul_rn(r[1], SPATIAL_SCALE));
        const int ys = (int)rintf(__fmul_rn(r[2], SPATIAL_SCALE));
        const int xe = (int)rintf(__fmul_rn(r[3], SPATIAL_SCALE));
        const int ye = (int)rintf(__fmul_rn(r[4], SPATIAL_SCALE));
        const float rw = (float)max(xe - xs + 1, 1);
        const float rh = (float)max(ye - ys + 1, 1);
        const float bh = __fmul_rn(rh, RCP_7);   // XLA reciprocal-multiply
        const float bw = __fmul_rn(rw, RCP_7);

        g_boff[roi] = b * (HW * C_DIM);
        #pragma unroll
        for (int p = 0; p < PH; ++p) {
            int hs = (int)floorf(__fmul_rn((float)p,        bh)) + ys;
            int he = (int)ceilf (__fmul_rn((float)p + 1.0f, bh)) + ys;
            int ws = (int)floorf(__fmul_rn((float)p,        bw)) + xs;
            int we = (int)ceilf (__fmul_rn((float)p + 1.0f, bw)) + xs;
            hs = min(max(hs, 0), H_DIM);
            he = min(max(he, 0), H_DIM);
            ws = min(max(ws, 0), W_DIM);
            we = min(max(we, 0), W_DIM);
            g_hs[roi * PH + p] = hs;
            g_he[roi * PH + p] = he;

            const int span = we - ws;   // in [.., 9]; <=0 means empty
            if (span >= 1) {
                const int k = 31 - __clz(span);          // floor(log2(span)), 0..3
                g_off[roi * PW + p] = make_int2(k * LVL_STRIDE + ws * C_DIM,
                                                k * LVL_STRIDE + (we - (1 << k)) * C_DIM);
            } else {
                g_off[roi * PW + p] = make_int2(-1, -1);
            }
        }
    }

    const int n   = blockIdx.z;
    const int hw0 = blockIdx.x * 32;
    const int c0b = blockIdx.y * 32;
    {
        const int c  = c0b + threadIdx.y;
        const int hw = hw0 + threadIdx.x;
        if (hw < HW) {
            tile[threadIdx.y][threadIdx.x] = x[(n * C_DIM + c) * HW + hw];
        }
    }
    __syncthreads();
    {
        const int hw = hw0 + threadIdx.y;
        const int c  = c0b + threadIdx.x;
        if (hw < HW) {
            g_tab[(size_t)(n * HW + hw) * C_DIM + c] = tile[threadIdx.x][threadIdx.y];
        }
    }
}

// ---------------------------------------------------------------------------
// Build sparse-table levels 1..3 from level 0.
// Grid = (50 h, 4 img, 2 c-halves). Block = 256 = 8 w-groups x 32 lanes.
// Each block loads one (img, h, 128-ch) row into smem once, then computes
// T1[w]=max(s[w..w+1]), T2[w]=max(s[w..w+3]), T3[w]=max(s[w..w+7]).
// ---------------------------------------------------------------------------
__global__ void __launch_bounds__(256) buildmax_kernel() {
    __shared__ float4 srow[W_DIM][32];   // 25600 B

    const int h  = blockIdx.x;
    const int n  = blockIdx.y;
    const int cz = blockIdx.z;           // channel half
    const int lane = threadIdx.x & 31;
    const int wg   = threadIdx.x >> 5;   // 8 w-groups

    const size_t rowbase = ((size_t)n * HW + (size_t)h * W_DIM) * C_DIM
                         + cz * 128 + lane * 4;

    for (int w = wg; w < W_DIM; w += 8) {
        srow[w][lane] = *(const float4*)&g_tab[rowbase + (size_t)w * C_DIM];
    }
    __syncthreads();

    for (int w = wg; w <= W_DIM - 2; w += 8) {
        const float4 s0 = srow[w][lane];
        const float4 s1 = srow[w + 1][lane];
        const float4 m1 = fmax4(s0, s1);
        *(float4*)&g_tab[1 * LVL_STRIDE + rowbase + (size_t)w * C_DIM] = m1;

        if (w <= W_DIM - 4) {
            const float4 s2 = srow[w + 2][lane];
            const float4 s3 = srow[w + 3][lane];
            const float4 m2 = fmax4(m1, fmax4(s2, s3));
            *(float4*)&g_tab[2 * LVL_STRIDE + rowbase + (size_t)w * C_DIM] = m2;

            if (w <= W_DIM - 8) {
                const float4 s4 = srow[w + 4][lane];
                const float4 s5 = srow[w + 5][lane];
                const float4 s6 = srow[w + 6][lane];
                const float4 s7 = srow[w + 7][lane];
                const float4 m3 = fmax4(m2, fmax4(fmax4(s4, s5), fmax4(s6, s7)));
                *(float4*)&g_tab[3 * LVL_STRIDE + rowbase + (size_t)w * C_DIM] = m3;
            }
        }
    }
}

// ---------------------------------------------------------------------------
// RoI max pooling via sparse-table lookups. One block per (roi, ph-row).
// Grid = 1024 x 7. Block = 256 = 4 pw-groups x 64 lanes (float4 -> 256 ch).
// Each pw-group handles pw = grp, then pw = grp + 4 (R9-proven skeleton).
// Per bin: w-max collapses to TWO table lookups per h-row; h handled by the
// proven 2-row diamond -> 4 independent LDG.128 in flight, ~2.2x less traffic.
// ---------------------------------------------------------------------------
__global__ void __launch_bounds__(256, 6) roipool_kernel(float* __restrict__ out) {
    __shared__ float s_out[C_DIM * PW];   // [c][pw] = 7168 B

    const int roi = blockIdx.x;
    const int ph  = blockIdx.y;

    const int boff = __ldg(&g_boff[roi]);
    const int hs   = __ldg(&g_hs[roi * PH + ph]);
    const int he   = __ldg(&g_he[roi * PH + ph]);

    const int lane = threadIdx.x & 63;   // 64 lanes -> 256 channels via float4
    const int grp  = threadIdx.x >> 6;   // 4 pw-groups
    const int c0   = lane * 4;

    #pragma unroll 1
    for (int it = 0; it < 2; ++it) {
        const int pw = it * 4 + grp;
        if (pw < PW) {
            const int2 off = __ldg(&g_off[roi * PW + pw]);

            float m0 = -INFINITY, m1 = -INFINITY, m2 = -INFINITY, m3 = -INFINITY;
            const bool empty = (hs >= he) || (off.x < 0);

            if (!empty) {
                const float* __restrict__ pA = g_tab + off.x + boff + c0;
                const float* __restrict__ pB = g_tab + off.y + boff + c0;

                int h = hs;
                #pragma unroll 1
                for (; h + 1 < he; h += 2) {       // 2-row diamond: 4 loads in flight
                    const float4 va = *(const float4*)(pA + h * ROW_STRIDE);
                    const float4 vb = *(const float4*)(pB + h * ROW_STRIDE);
                    const float4 vc = *(const float4*)(pA + (h + 1) * ROW_STRIDE);
                    const float4 vd = *(const float4*)(pB + (h + 1) * ROW_STRIDE);
                    m0 = fmaxf(fmaxf(fmaxf(m0, va.x), vb.x), fmaxf(vc.x, vd.x));
                    m1 = fmaxf(fmaxf(fmaxf(m1, va.y), vb.y), fmaxf(vc.y, vd.y));
                    m2 = fmaxf(fmaxf(fmaxf(m2, va.z), vb.z), fmaxf(vc.z, vd.z));
                    m3 = fmaxf(fmaxf(fmaxf(m3, va.w), vb.w), fmaxf(vc.w, vd.w));
                }
                if (h < he) {                      // remainder row: 2 loads
                    const float4 va = *(const float4*)(pA + h * ROW_STRIDE);
                    const float4 vb = *(const float4*)(pB + h * ROW_STRIDE);
                    m0 = fmaxf(m0, fmaxf(va.x, vb.x));
                    m1 = fmaxf(m1, fmaxf(va.y, vb.y));
                    m2 = fmaxf(m2, fmaxf(va.z, vb.z));
                    m3 = fmaxf(m3, fmaxf(va.w, vb.w));
                }
            } else {
                m0 = m1 = m2 = m3 = 0.0f;          // empty bin -> 0
            }

            s_out[(c0 + 0) * PW + pw] = m0;
            s_out[(c0 + 1) * PW + pw] = m1;
            s_out[(c0 + 2) * PW + pw] = m2;
            s_out[(c0 + 3) * PW + pw] = m3;
        }
    }
    __syncthreads();

    // Store: out[roi, c, ph, pw] = s_out[c*7 + pw].
    float* __restrict__ obase = out + (size_t)roi * OUT_PER_ROI + ph * PW;
    #pragma unroll 1
    for (int i = threadIdx.x; i < C_DIM * PW; i += 256) {
        const int c  = i / PW;
        const int pw = i - c * PW;
        obase[c * NBINS + pw] = s_out[i];
    }
}

extern "C" void kernel_launch(void* const* d_in, const int* in_sizes, int n_in,
                              void* d_out, int out_size) {
    const float* x    = (const float*)d_in[0];
    const float* rois = (const float*)d_in[1];
    float* out        = (float*)d_out;

    (void)in_sizes; (void)n_in; (void)out_size;

    dim3 tgrid((HW + 31) / 32, C_DIM / 32, N_IMG);
    dim3 tblk(32, 32);
    transpose_kernel<<<tgrid, tblk>>>(x, rois);

    dim3 bgrid(H_DIM, N_IMG, 2);
    buildmax_kernel<<<bgrid, 256>>>();

    dim3 pgrid(N_ROI, PH);
    roipool_kernel<<<pgrid, 256>>>(out);
}

// round 16
// speedup vs baseline: 1.1850x; 1.0081x over previous
#include <cuda_runtime.h>
#include <math.h>

// Problem constants
#define N_IMG 4
#define C_DIM 256
#define H_DIM 50
#define W_DIM 50
#define HW (H_DIM * W_DIM)
#define PH 7
#define PW 7
#define NBINS (PH * PW)
#define N_ROI 1024
#define OUT_PER_ROI (C_DIM * NBINS)   // 12544 floats
#define SPATIAL_SCALE 0.0625f
#define ROW_STRIDE (W_DIM * C_DIM)    // floats per h-row (within a level)
#define LVL_STRIDE (N_IMG * HW * C_DIM)   // floats per sparse-table level

// fl(1/7) in fp32 — XLA rewrites (x / 7) into (x * fl(1/7)); we must match it.
#define RCP_7 0.14285714924335479736328125f

// Sparse range-max table, 4 levels. Level 0 = transposed input (NHWC).
// T_k[n][h][w][c] = max over w' in [w, w+2^k) of x_nhwc. 40.96 MB (fits L2).
__device__ float g_tab[4 * LVL_STRIDE];

// Precomputed per-roi geometry (exact XLA numerics, computed once)
__device__ int  g_boff[N_ROI];        // image offset within a level (floats)
__device__ int  g_hs[N_ROI * PH];
__device__ int  g_he[N_ROI * PH];
__device__ int2 g_off[N_ROI * PW];    // (offA, offB) = level+column float offsets
                                      // offA < 0 marks an empty w-window

// ---------------------------------------------------------------------------
// FUSED transpose + sparse-table build. One block per (h, img, 32-ch strip):
// grid = (50, 4, 8), block = 256.
//  - Load 32c x 50w NCHW tile into smem (rows contiguous in w).
//  - Threads = 8 w-groups x 32 c-lanes; per w: read s[w..w+7] from smem
//    (51-padding -> conflict-free), emit levels 0..3 NHWC-coalesced
//    (32 consecutive c per store = 128B lines).
// Block (0,0,0) also precomputes all roi bin edges + lookup offsets
// (256 threads x 4 rois, exact XLA numerics).
// ---------------------------------------------------------------------------
__global__ void __launch_bounds__(256) buildtab_kernel(const float* __restrict__ x,
                                                       const float* __restrict__ rois) {
    __shared__ float tile[32][51];   // [c_local][w], pad 51: gcd(51,32)=1

    if (blockIdx.x == 0 && blockIdx.y == 0 && blockIdx.z == 0) {
        const int tid = threadIdx.x;
        #pragma unroll
        for (int q = 0; q < 4; ++q) {
            const int roi = tid * 4 + q;   // 0..1023
            const float* r = rois + roi * 5;
            const int b  = (int)r[0];
            const int xs = (int)rintf(__fmul_rn(r[1], SPATIAL_SCALE));
            const int ys = (int)rintf(__fmul_rn(r[2], SPATIAL_SCALE));
            const int xe = (int)rintf(__fmul_rn(r[3], SPATIAL_SCALE));
            const int ye = (int)rintf(__fmul_rn(r[4], SPATIAL_SCALE));
            const float rw = (float)max(xe - xs + 1, 1);
            const float rh = (float)max(ye - ys + 1, 1);
            const float bh = __fmul_rn(rh, RCP_7);   // XLA reciprocal-multiply
            const float bw = __fmul_rn(rw, RCP_7);

            g_boff[roi] = b * (HW * C_DIM);
            #pragma unroll
            for (int p = 0; p < PH; ++p) {
                int hs = (int)floorf(__fmul_rn((float)p,        bh)) + ys;
                int he = (int)ceilf (__fmul_rn((float)p + 1.0f, bh)) + ys;
                int ws = (int)floorf(__fmul_rn((float)p,        bw)) + xs;
                int we = (int)ceilf (__fmul_rn((float)p + 1.0f, bw)) + xs;
                hs = min(max(hs, 0), H_DIM);
                he = min(max(he, 0), H_DIM);
                ws = min(max(ws, 0), W_DIM);
                we = min(max(we, 0), W_DIM);
                g_hs[roi * PH + p] = hs;
                g_he[roi * PH + p] = he;

                const int span = we - ws;   // <= 9; <=0 means empty
                if (span >= 1) {
                    const int k = 31 - __clz(span);   // floor(log2(span)), 0..3
                    g_off[roi * PW + p] =
                        make_int2(k * LVL_STRIDE + ws * C_DIM,
                                  k * LVL_STRIDE + (we - (1 << k)) * C_DIM);
                } else {
                    g_off[roi * PW + p] = make_int2(-1, -1);
                }
            }
        }
    }

    const int h  = blockIdx.x;
    const int n  = blockIdx.y;
    const int c0 = blockIdx.z * 32;

    // Load NCHW tile: 32 c-rows of 50 contiguous floats each.
    #pragma unroll 1
    for (int i = threadIdx.x; i < 32 * W_DIM; i += 256) {
        const int c = i / W_DIM;
        const int w = i - c * W_DIM;
        tile[c][w] = x[((size_t)(n * C_DIM + c0 + c) * H_DIM + h) * W_DIM + w];
    }
    __syncthreads();

    const int lane = threadIdx.x & 31;   // c within strip
    const int wg   = threadIdx.x >> 5;   // 8 w-groups

    const size_t outbase = ((size_t)n * HW + (size_t)h * W_DIM) * C_DIM + c0 + lane;

    #pragma unroll 1
    for (int w = wg; w < W_DIM; w += 8) {
        const float s0 = tile[lane][w];
        g_tab[outbase + (size_t)w * C_DIM] = s0;                       // level 0

        if (w <= W_DIM - 2) {
            const float m1 = fmaxf(s0, tile[lane][w + 1]);
            g_tab[1 * LVL_STRIDE + outbase + (size_t)w * C_DIM] = m1;  // level 1

            if (w <= W_DIM - 4) {
                const float m2 = fmaxf(m1, fmaxf(tile[lane][w + 2], tile[lane][w + 3]));
                g_tab[2 * LVL_STRIDE + outbase + (size_t)w * C_DIM] = m2;  // level 2

                if (w <= W_DIM - 8) {
                    const float m3 = fmaxf(m2,
                        fmaxf(fmaxf(tile[lane][w + 4], tile[lane][w + 5]),
                              fmaxf(tile[lane][w + 6], tile[lane][w + 7])));
                    g_tab[3 * LVL_STRIDE + outbase + (size_t)w * C_DIM] = m3;  // level 3
                }
            }
        }
    }
}

// ---------------------------------------------------------------------------
// RoI max pooling via sparse-table lookups — UNCHANGED from R15 (proven).
// One block per (roi, ph-row). Grid = 1024 x 7.
// Block = 256 = 4 pw-groups x 64 lanes (float4 -> 256 ch).
// Per bin: w-max = TWO table lookups per h-row; 2-row diamond -> 4
// independent LDG.128 in flight.
// ---------------------------------------------------------------------------
__global__ void __launch_bounds__(256, 6) roipool_kernel(float* __restrict__ out) {
    __shared__ float s_out[C_DIM * PW];   // [c][pw] = 7168 B

    const int roi = blockIdx.x;
    const int ph  = blockIdx.y;

    const int boff = __ldg(&g_boff[roi]);
    const int hs   = __ldg(&g_hs[roi * PH + ph]);
    const int he   = __ldg(&g_he[roi * PH + ph]);

    const int lane = threadIdx.x & 63;   // 64 lanes -> 256 channels via float4
    const int grp  = threadIdx.x >> 6;   // 4 pw-groups
    const int c0   = lane * 4;

    #pragma unroll 1
    for (int it = 0; it < 2; ++it) {
        const int pw = it * 4 + grp;
        if (pw < PW) {
            const int2 off = __ldg(&g_off[roi * PW + pw]);

            float m0 = -INFINITY, m1 = -INFINITY, m2 = -INFINITY, m3 = -INFINITY;
            const bool empty = (hs >= he) || (off.x < 0);

            if (!empty) {
                const float* __restrict__ pA = g_tab + off.x + boff + c0;
                const float* __restrict__ pB = g_tab + off.y + boff + c0;

                int h = hs;
                #pragma unroll 1
                for (; h + 1 < he; h += 2) {       // 2-row diamond: 4 loads in flight
                    const float4 va = *(const float4*)(pA + h * ROW_STRIDE);
                    const float4 vb = *(const float4*)(pB + h * ROW_STRIDE);
                    const float4 vc = *(const float4*)(pA + (h + 1) * ROW_STRIDE);
                    const float4 vd = *(const float4*)(pB + (h + 1) * ROW_STRIDE);
                    m0 = fmaxf(fmaxf(fmaxf(m0, va.x), vb.x), fmaxf(vc.x, vd.x));
                    m1 = fmaxf(fmaxf(fmaxf(m1, va.y), vb.y), fmaxf(vc.y, vd.y));
                    m2 = fmaxf(fmaxf(fmaxf(m2, va.z), vb.z), fmaxf(vc.z, vd.z));
                    m3 = fmaxf(fmaxf(fmaxf(m3, va.w), vb.w), fmaxf(vc.w, vd.w));
                }
                if (h < he) {                      // remainder row: 2 loads
                    const float4 va = *(const float4*)(pA + h * ROW_STRIDE);
                    const float4 vb = *(const float4*)(pB + h * ROW_STRIDE);
                    m0 = fmaxf(m0, fmaxf(va.x, vb.x));
                    m1 = fmaxf(m1, fmaxf(va.y, vb.y));
                    m2 = fmaxf(m2, fmaxf(va.z, vb.z));
                    m3 = fmaxf(m3, fmaxf(va.w, vb.w));
                }
            } else {
                m0 = m1 = m2 = m3 = 0.0f;          // empty bin -> 0
            }

            s_out[(c0 + 0) * PW + pw] = m0;
            s_out[(c0 + 1) * PW + pw] = m1;
            s_out[(c0 + 2) * PW + pw] = m2;
            s_out[(c0 + 3) * PW + pw] = m3;
        }
    }
    __syncthreads();

    // Store: out[roi, c, ph, pw] = s_out[c*7 + pw].
    float* __restrict__ obase = out + (size_t)roi * OUT_PER_ROI + ph * PW;
    #pragma unroll 1
    for (int i = threadIdx.x; i < C_DIM * PW; i += 256) {
        const int c  = i / PW;
        const int pw = i - c * PW;
        obase[c * NBINS + pw] = s_out[i];
    }
}

extern "C" void kernel_launch(void* const* d_in, const int* in_sizes, int n_in,
                              void* d_out, int out_size) {
    const float* x    = (const float*)d_in[0];
    const float* rois = (const float*)d_in[1];
    float* out        = (float*)d_out;

    (void)in_sizes; (void)n_in; (void)out_size;

    dim3 bgrid(H_DIM, N_IMG, C_DIM / 32);   // 50 x 4 x 8 = 1600 blocks
    buildtab_kernel<<<bgrid, 256>>>(x, rois);

    dim3 pgrid(N_ROI, PH);
    roipool_kernel<<<pgrid, 256>>>(out);
}